// round 14
// baseline (speedup 1.0000x reference)
#include <cuda_runtime.h>
#include <cuda_fp16.h>
#include <math.h>

#define NCH 4
#define NN 20000
#define NE 320000
#define NT 16
#define HID 32
#define CHUNK 2048
#define NCHK 10    // scanC chunks (2048 nodes)
#define PCHUNK 1024
#define NPCH 20    // prefA chunks (1024 nodes)
#define CAP 64     // per-warp p-tile capacity in l2_gather
#define NBLK 16    // histogram blocks per edge type
#define SL (NE/NBLK)

// edge-type metadata: 4 spatial (c->c) then 12 inter-channel (s!=d)
__constant__ int c_src[16] = {0,1,2,3, 0,0,0, 1,1,1, 2,2,2, 3,3,3};
__constant__ int c_dst[16] = {0,1,2,3, 1,2,3, 0,2,3, 0,1,3, 0,1,2};
__constant__ int c_in[4][4]  = {{0,7,10,13},{1,4,11,14},{2,5,8,15},{3,6,9,12}};  // dst==c
__constant__ int c_out[4][4] = {{0,4,5,6},{1,7,8,9},{2,10,11,12},{3,13,14,15}};  // src==c

// scratch (static device globals; no allocation)
__device__ int    g_pc[NT*NBLK*NN];     // per-(type,block) partial counts -> prefixes
__device__ int    g_cnt[NT*NN];         // per-(type,node) total counts
__device__ int    g_off[NT*(NN+1)];
__device__ int    g_col[NT*NE];
__device__ int    g_bsum[NT*NPCH];
__device__ float4 g_za[NT*NN];          // layer1 per-(type,dst) head aggregates
__device__ __half g_y[NCH*NN*HID];      // layer1 output (post relu), fp16 for gather BW
__device__ float4 g_s2[NT*NN];          // layer2 src scores per head
__device__ float4 g_d2[NT*NN];          // layer2 dst scores per head
__device__ float4 g_As2[NT*HID];        // W2^T @ att_src2 folded: [t][f][h]
__device__ float4 g_Ad2[NT*HID];
__device__ float4 g_SA[NT];             // layer1 folded score weights [t][h]
__device__ float4 g_DA[NT];
__device__ float4 g_Wt[NT*HID*HID];     // W2 transposed: [t][f][j] = {W2[t][f][h*32+j]}_h

__device__ __forceinline__ float lrelu(float v){ return v > 0.f ? v : 0.2f*v; }

// ---- packed f32x2 helpers (sm_103a) ----
__device__ __forceinline__ unsigned long long pk2(float lo, float hi){
    unsigned long long r;
    asm("mov.b64 %0, {%1, %2};" : "=l"(r) : "f"(lo), "f"(hi));
    return r;
}
__device__ __forceinline__ void fma2(unsigned long long& d, unsigned long long a,
                                     unsigned long long b){
    asm("fma.rn.f32x2 %0, %1, %2, %3;" : "=l"(d) : "l"(a), "l"(b), "l"(d));
}
__device__ __forceinline__ void mul2(unsigned long long& d, unsigned long long a,
                                     unsigned long long b){
    asm("mul.rn.f32x2 %0, %1, %2;" : "=l"(d) : "l"(a), "l"(b));
}
__device__ __forceinline__ void add2(unsigned long long& d, unsigned long long a,
                                     unsigned long long b){
    asm("add.rn.f32x2 %0, %1, %2;" : "=l"(d) : "l"(a), "l"(b));
}
__device__ __forceinline__ float2 upk2(unsigned long long v){
    float2 r;
    asm("mov.b64 {%0, %1}, %2;" : "=f"(r.x), "=f"(r.y) : "l"(v));
    return r;
}

// ---------------- CSR: smem histogram count (no rank storage) ----------------
__global__ void __launch_bounds__(1024) count_kernel(const int* __restrict__ edges){
    extern __shared__ int hist[];           // [NN] = 80 KB
    int b = blockIdx.x;                     // b = t*NBLK + blk
    int t = b >> 4, blk = b & 15;
    for (int i = threadIdx.x; i < NN; i += 1024) hist[i] = 0;
    __syncthreads();
    const int4* dstp = (const int4*)(edges + t*2*NE + NE + blk*SL);
    for (int i = threadIdx.x; i < SL/8; i += 1024){
        int4 dA = dstp[2*i];
        int4 dB = dstp[2*i+1];
        atomicAdd(&hist[dA.x], 1);
        atomicAdd(&hist[dA.y], 1);
        atomicAdd(&hist[dA.z], 1);
        atomicAdd(&hist[dA.w], 1);
        atomicAdd(&hist[dB.x], 1);
        atomicAdd(&hist[dB.y], 1);
        atomicAdd(&hist[dB.z], 1);
        atomicAdd(&hist[dB.w], 1);
    }
    __syncthreads();
    int* pc = g_pc + b*NN;
    for (int i = threadIdx.x; i < NN; i += 1024) pc[i] = hist[i];
}

// ---------------- merged: per-node prefix over NBLK partials + chunk sums ------
__global__ void __launch_bounds__(256) prefA_kernel(){
    __shared__ int sd[256];
    int b = blockIdx.x;                     // b = t*NPCH + chunk
    int t = b / NPCH, chunk = b % NPCH;
    int tid = threadIdx.x;
    int base = chunk*PCHUNK + tid*4;        // NN%4==0 -> base<NN implies base+4<=NN
    int v[NBLK][4];
    bool ok = base < NN;
    #pragma unroll
    for (int k = 0; k < NBLK; k++){
        int4 a = make_int4(0,0,0,0);
        if (ok) a = *(const int4*)(g_pc + (t*NBLK + k)*NN + base);
        v[k][0]=a.x; v[k][1]=a.y; v[k][2]=a.z; v[k][3]=a.w;
    }
    int cnt[4];
    int tsum = 0;
    #pragma unroll
    for (int e = 0; e < 4; e++){
        int run = 0;
        #pragma unroll
        for (int k = 0; k < NBLK; k++){
            int tmp = v[k][e];
            v[k][e] = run;                  // exclusive prefix across blocks
            run += tmp;
        }
        cnt[e] = run;
        tsum += run;
    }
    if (ok){
        #pragma unroll
        for (int k = 0; k < NBLK; k++)
            *(int4*)(g_pc + (t*NBLK + k)*NN + base) =
                make_int4(v[k][0], v[k][1], v[k][2], v[k][3]);
        *(int4*)(g_cnt + t*NN + base) = make_int4(cnt[0], cnt[1], cnt[2], cnt[3]);
    }
    sd[tid] = tsum;
    __syncthreads();
    #pragma unroll
    for (int ofs = 128; ofs > 0; ofs >>= 1){
        if (tid < ofs) sd[tid] += sd[tid+ofs];
        __syncthreads();
    }
    if (tid == 0) g_bsum[b] = sd[0];
}

// ---------------- scan: per-chunk exclusive scan -> g_off (bbase inline) -------
__global__ void __launch_bounds__(256) scanC_kernel(){
    __shared__ int sd[256];
    __shared__ int bb;
    int b = blockIdx.x;
    int t = b / NCHK, chunk = b % NCHK;
    int tid = threadIdx.x;
    if (tid == 0){
        int run = 0;
        for (int k = 0; k < 2*chunk; k++) run += g_bsum[t*NPCH + k];
        bb = run;
        if (chunk == 0) g_off[t*(NN+1)] = 0;
    }
    int base = chunk*CHUNK + tid*8;
    int c[8];
    int tsum = 0;
    bool ok = base < NN;
    {
        int4 a = make_int4(0,0,0,0), d = make_int4(0,0,0,0);
        if (ok){
            const int4* p = (const int4*)(g_cnt + t*NN + base);
            a = p[0]; d = p[1];
        }
        c[0]=a.x; c[1]=a.y; c[2]=a.z; c[3]=a.w;
        c[4]=d.x; c[5]=d.y; c[6]=d.z; c[7]=d.w;
        #pragma unroll
        for (int e = 0; e < 8; e++) tsum += c[e];
    }
    sd[tid] = tsum;
    __syncthreads();
    #pragma unroll
    for (int ofs = 1; ofs < 256; ofs <<= 1){
        int add = (tid >= ofs) ? sd[tid-ofs] : 0;
        __syncthreads();
        sd[tid] += add;
        __syncthreads();
    }
    int run = sd[tid] - tsum + bb;
    if (ok){
        #pragma unroll
        for (int e = 0; e < 8; e++){
            run += c[e];
            g_off[t*(NN+1) + base + e + 1] = run;
        }
    }
}

// ---------------- CSR: fill via seeded smem cursors ----------------
__global__ void __launch_bounds__(1024) fill2_kernel(const int* __restrict__ edges){
    extern __shared__ int cur[];            // [NN] = 80 KB
    int b = blockIdx.x;
    int t = b >> 4, blk = b & 15;
    const int* offT = g_off + t*(NN+1);
    const int* pc = g_pc + b*NN;
    for (int i = threadIdx.x; i < NN; i += 1024) cur[i] = offT[i] + pc[i];
    __syncthreads();
    const int4* srcp = (const int4*)(edges + t*2*NE + blk*SL);
    const int4* dstp = (const int4*)(edges + t*2*NE + NE + blk*SL);
    int* colT = g_col + t*NE;
    for (int i = threadIdx.x; i < SL/8; i += 1024){
        int4 sA = srcp[2*i],  sB = srcp[2*i+1];
        int4 dA = dstp[2*i],  dB = dstp[2*i+1];
        int pA0 = atomicAdd(&cur[dA.x], 1);
        int pA1 = atomicAdd(&cur[dA.y], 1);
        int pA2 = atomicAdd(&cur[dA.z], 1);
        int pA3 = atomicAdd(&cur[dA.w], 1);
        int pB0 = atomicAdd(&cur[dB.x], 1);
        int pB1 = atomicAdd(&cur[dB.y], 1);
        int pB2 = atomicAdd(&cur[dB.z], 1);
        int pB3 = atomicAdd(&cur[dB.w], 1);
        colT[pA0] = sA.x;
        colT[pA1] = sA.y;
        colT[pA2] = sA.z;
        colT[pA3] = sA.w;
        colT[pB0] = sB.x;
        colT[pB1] = sB.y;
        colT[pB2] = sB.z;
        colT[pB3] = sB.w;
    }
}

// ---------------- fold attention weights + transpose W2 (merged) ----------------
__global__ void paramwt_kernel(const float* __restrict__ W1, const float* __restrict__ as1,
                               const float* __restrict__ ad1,
                               const float* __restrict__ W2, const float* __restrict__ as2,
                               const float* __restrict__ ad2){
    int i = blockIdx.x*blockDim.x + threadIdx.x;
    if (i >= NT*HID*HID) return;
    int t = i >> 10;
    int r = i & 1023;
    int f = r >> 5, j = r & 31;
    const float* wb = W2 + (t*HID + f)*128 + j;
    g_Wt[i] = make_float4(wb[0], wb[32], wb[64], wb[96]);
    if (j < 4){
        int h = j;
        float sa = 0.f, sd = 0.f;
        const float* wrow = W2 + (t*HID + f)*128 + h*32;
        const float* arow = as2 + (t*4 + h)*32;
        const float* drow = ad2 + (t*4 + h)*32;
        #pragma unroll
        for (int c = 0; c < 32; c++){ sa += wrow[c]*arow[c]; sd += wrow[c]*drow[c]; }
        ((float*)g_As2)[(t*HID + f)*4 + h] = sa;
        ((float*)g_Ad2)[(t*HID + f)*4 + h] = sd;
        if (f == 0){
            float s1 = 0.f, d1 = 0.f;
            const float* w1 = W1 + t*128 + h*32;
            const float* a1 = as1 + (t*4 + h)*32;
            const float* dd1 = ad1 + (t*4 + h)*32;
            #pragma unroll
            for (int c = 0; c < 32; c++){ s1 += w1[c]*a1[c]; d1 += w1[c]*dd1[c]; }
            ((float*)g_SA)[t*4 + h] = s1;
            ((float*)g_DA)[t*4 + h] = d1;
        }
    }
}

// ---------------- layer-1 edge aggregation: thread per (type,dst), 4-edge ILP ----
__global__ void l1_edge_kernel(const float* __restrict__ x){
    int i = blockIdx.x*blockDim.x + threadIdx.x;
    if (i >= NT*NN) return;
    int t = i / NN, n = i - t*NN;
    float4 SAv = g_SA[t];
    float4 DAv = g_DA[t];
    float SA[4] = {SAv.x, SAv.y, SAv.z, SAv.w};
    float DA[4] = {DAv.x, DAv.y, DAv.z, DAv.w};
    float xd = x[c_dst[t]*NN + n];
    float dsc[4];
    #pragma unroll
    for (int h = 0; h < 4; h++) dsc[h] = xd * DA[h];
    const float* xs = x + c_src[t]*NN;
    const int* col = g_col + t*NE;
    int beg = g_off[t*(NN+1) + n];
    int end = g_off[t*(NN+1) + n + 1];
    float den[4] = {0,0,0,0}, acc[4] = {0,0,0,0};
    int j = beg;
    for (; j + 3 < end; j += 4){         // 4 independent x gathers in flight
        int s0 = col[j], s1 = col[j+1], s2 = col[j+2], s3 = col[j+3];
        float x0 = xs[s0], x1 = xs[s1], x2 = xs[s2], x3 = xs[s3];
        #pragma unroll
        for (int h = 0; h < 4; h++){
            float p0 = __expf(lrelu(x0*SA[h] + dsc[h]));
            float p1 = __expf(lrelu(x1*SA[h] + dsc[h]));
            float p2 = __expf(lrelu(x2*SA[h] + dsc[h]));
            float p3 = __expf(lrelu(x3*SA[h] + dsc[h]));
            den[h] += (p0 + p1) + (p2 + p3);
            acc[h] += (p0*x0 + p1*x1) + (p2*x2 + p3*x3);
        }
    }
    for (; j < end; j++){
        int s = col[j];
        float xv = xs[s];
        #pragma unroll
        for (int h = 0; h < 4; h++){
            float p = __expf(lrelu(xv*SA[h] + dsc[h]));
            den[h] += p;
            acc[h] += p*xv;
        }
    }
    float4 z;
    z.x = den[0] > 0.f ? acc[0]/den[0] : 0.f;
    z.y = den[1] > 0.f ? acc[1]/den[1] : 0.f;
    z.z = den[2] > 0.f ? acc[2]/den[2] : 0.f;
    z.w = den[3] > 0.f ? acc[3]/den[3] : 0.f;
    g_za[t*NN + n] = z;
}

// ---------------- layer-1 combine + layer-2 scores (fused, warp per node) -------
// lane = feature j for y; then lane = (k, src/dst, head) for the 32 score
// outputs, each computed via 32 shfl-broadcasts of v against L1-resident
// folded coefficients. Scores use fp32 v; only the stored y sees fp16.
__global__ void l1cs_kernel(const float* __restrict__ W1, const float* __restrict__ b1){
    int wg = blockIdx.x*8 + (threadIdx.x >> 5);
    int lane = threadIdx.x & 31;
    int c = wg / NN, n = wg - c*NN;
    int j = lane;
    float v = 0.f;
    #pragma unroll
    for (int k = 0; k < 4; k++){
        int t = c_in[c][k];
        float4 za = g_za[t*NN + n];
        const float* w = W1 + t*128;
        float o = za.x*w[j] + za.y*w[32+j] + za.z*w[64+j] + za.w*w[96+j];
        v += o*0.25f + b1[t*HID + j];
    }
    v *= 0.25f;                       // hetero mean over 4 incoming types
    v = v > 0.f ? v : 0.f;
    g_y[c*NN*HID + n*HID + j] = __float2half_rn(v);
    // one score per lane: k = lane>>3, sd = (lane>>2)&1, h = lane&3
    int k = lane >> 3, sd = (lane >> 2) & 1, h = lane & 3;
    int t = sd ? c_in[c][k] : c_out[c][k];
    const float* tbl = sd ? (const float*)g_Ad2 : (const float*)g_As2;
    const float* coef = tbl + t*HID*4 + h;
    float acc = 0.f;
    #pragma unroll
    for (int f = 0; f < 32; f++){
        float yf = __shfl_sync(0xffffffffu, v, f);
        acc += yf * coef[f*4];
    }
    float* dst = sd ? (float*)g_d2 : (float*)g_s2;
    dst[(t*NN + n)*4 + h] = acc;
}

// ---------------- layer-2 fused: softmax + gather + block-GEMM epilogue ----------
// Phase 1: warp per dst node; exp lane-parallel into p-tiles; gather stage
// PAIRED: half-warp per edge (16 lanes x half2 = one 64B fp16 y row), two
// edges per iteration, halves recombined with one 64-bit shfl at the end.
__global__ void __launch_bounds__(1024) l2_gather_kernel(const float* __restrict__ b2,
                                                         float* __restrict__ out){
    extern __shared__ float smemf[];
    float4* zsm = (float4*)smemf;                 // [4][32n][32f] f4(h): 64 KB
    float4* wbA = (float4*)(smemf + 16384);       // [32 warps][CAP]:     32 KB
    int*    cbA = (int*)  (smemf + 24576);        // [32 warps][CAP]:      8 KB
    float*  psum = (float*)wbA;                   // reused in phase 2:   16 KB
    int c = blockIdx.y;
    int tid = threadIdx.x;
    int warp = tid >> 5, lane = tid & 31;
    int half = lane >> 4, fl = lane & 15;
    int n = blockIdx.x*32 + warp;                 // grid.x = 625, exact cover
    float4* wb = wbA + warp*CAP;
    int* cb = cbA + warp*CAP;
    #pragma unroll
    for (int k = 0; k < 4; k++){
        int t = c_in[c][k];
        const __half* ysrc = g_y + c_src[t]*NN*HID;
        const int* col = g_col + t*NE;
        const float4* s2 = g_s2 + t*NN;
        int beg = g_off[t*(NN+1) + n], end = g_off[t*(NN+1) + n + 1];
        int deg = end - beg;
        float4 dv = g_d2[t*NN + n];
        float d0 = 0.f, d1 = 0.f, d2 = 0.f, d3 = 0.f;
        unsigned long long a01 = 0ull, a23 = 0ull;
        if (deg <= CAP){
            int degE = (deg + 1) & ~1;            // pad to even
            for (int base = 0; base < degE; base += 32){
                int j = base + lane;
                if (j < deg){
                    int s = col[beg + j];
                    float4 sv = s2[s];
                    float4 p;
                    p.x = __expf(lrelu(sv.x + dv.x));
                    p.y = __expf(lrelu(sv.y + dv.y));
                    p.z = __expf(lrelu(sv.z + dv.z));
                    p.w = __expf(lrelu(sv.w + dv.w));
                    d0 += p.x; d1 += p.y; d2 += p.z; d3 += p.w;
                    wb[j] = p; cb[j] = s;
                } else if (j < degE){
                    wb[j] = make_float4(0.f, 0.f, 0.f, 0.f);
                    cb[j] = 0;
                }
            }
            __syncwarp();
            #pragma unroll
            for (int o = 16; o; o >>= 1){
                d0 += __shfl_xor_sync(0xffffffffu, d0, o);
                d1 += __shfl_xor_sync(0xffffffffu, d1, o);
                d2 += __shfl_xor_sync(0xffffffffu, d2, o);
                d3 += __shfl_xor_sync(0xffffffffu, d3, o);
            }
            // paired gather: half-warp h processes edge i+h; lane owns features
            // 2*fl, 2*fl+1 via one half2 load (16 lanes cover the 64B row).
            unsigned long long cA01 = 0ull, cA23 = 0ull;   // feature 2*fl
            unsigned long long cB01 = 0ull, cB23 = 0ull;   // feature 2*fl+1
            for (int i = 0; i < degE; i += 2){
                int e = i + half;
                int s = cb[e];
                ulonglong2 pw = *(const ulonglong2*)(wb + e);
                float2 yv = __half22float2(*(const __half2*)(ysrc + s*HID + 2*fl));
                unsigned long long y0 = pk2(yv.x, yv.x);
                unsigned long long y1 = pk2(yv.y, yv.y);
                fma2(cA01, pw.x, y0); fma2(cA23, pw.y, y0);
                fma2(cB01, pw.x, y1); fma2(cB23, pw.y, y1);
            }
            // recombine halves (lane l <-> l^16 hold same features, other edges)
            add2(cA01, cA01, __shfl_xor_sync(0xffffffffu, cA01, 16));
            add2(cA23, cA23, __shfl_xor_sync(0xffffffffu, cA23, 16));
            add2(cB01, cB01, __shfl_xor_sync(0xffffffffu, cB01, 16));
            add2(cB23, cB23, __shfl_xor_sync(0xffffffffu, cB23, 16));
            unsigned long long r01 = pk2(d0 > 0.f ? __fdividef(0.25f, d0) : 0.f,
                                         d1 > 0.f ? __fdividef(0.25f, d1) : 0.f);
            unsigned long long r23 = pk2(d2 > 0.f ? __fdividef(0.25f, d2) : 0.f,
                                         d3 > 0.f ? __fdividef(0.25f, d3) : 0.f);
            // lane writes feature f = 2*fl + half (both halves have full sums)
            unsigned long long w01 = half ? cB01 : cA01;
            unsigned long long w23 = half ? cB23 : cA23;
            mul2(w01, w01, r01);
            mul2(w23, w23, r23);
            int f = 2*fl + half;
            *(ulonglong2*)(zsm + (k*32 + warp)*32 + f) = make_ulonglong2(w01, w23);
            __syncwarp();
        } else {                                  // rare fallback: recompute path
            for (int base = beg; base < end; base += 32){
                int j = base + lane;
                if (j < end){
                    int s = col[j];
                    float4 sv = s2[s];
                    d0 += __expf(lrelu(sv.x + dv.x));
                    d1 += __expf(lrelu(sv.y + dv.y));
                    d2 += __expf(lrelu(sv.z + dv.z));
                    d3 += __expf(lrelu(sv.w + dv.w));
                }
            }
            #pragma unroll
            for (int o = 16; o; o >>= 1){
                d0 += __shfl_xor_sync(0xffffffffu, d0, o);
                d1 += __shfl_xor_sync(0xffffffffu, d1, o);
                d2 += __shfl_xor_sync(0xffffffffu, d2, o);
                d3 += __shfl_xor_sync(0xffffffffu, d3, o);
            }
            for (int base = beg; base < end; base += 32){
                int j = base + lane;
                int m = min(32, end - base);
                if (j < end){
                    int s = col[j];
                    float4 sv = s2[s];
                    float4 p;
                    p.x = __expf(lrelu(sv.x + dv.x));
                    p.y = __expf(lrelu(sv.y + dv.y));
                    p.z = __expf(lrelu(sv.z + dv.z));
                    p.w = __expf(lrelu(sv.w + dv.w));
                    wb[lane] = p; cb[lane] = s;
                }
                __syncwarp();
                for (int i = 0; i < m; i++){
                    ulonglong2 pw = *(const ulonglong2*)(wb + i);
                    float yv = __half2float(ysrc[cb[i]*HID + lane]);
                    unsigned long long y2 = pk2(yv, yv);
                    fma2(a01, pw.x, y2); fma2(a23, pw.y, y2);
                }
                __syncwarp();
            }
            unsigned long long r01 = pk2(d0 > 0.f ? __fdividef(0.25f, d0) : 0.f,
                                         d1 > 0.f ? __fdividef(0.25f, d1) : 0.f);
            unsigned long long r23 = pk2(d2 > 0.f ? __fdividef(0.25f, d2) : 0.f,
                                         d3 > 0.f ? __fdividef(0.25f, d3) : 0.f);
            mul2(a01, a01, r01);
            mul2(a23, a23, r23);
            *(ulonglong2*)(zsm + (k*32 + warp)*32 + lane) = make_ulonglong2(a01, a23);
        }
    }
    __syncthreads();
    // phase 2: block GEMM, 2x2 tiles, k split over thread groups; Wt from L1
    {
        int g  = tid >> 8;            // k
        int r  = tid & 255;
        int tn = r >> 4;              // 0..15
        int tj = r & 15;              // 0..15
        const float4* Zk = zsm + g*1024;
        const float4* Wk = g_Wt + c_in[c][g]*1024;
        unsigned long long aA00=0ull, aB00=0ull, aA01=0ull, aB01=0ull;
        unsigned long long aA10=0ull, aB10=0ull, aA11=0ull, aB11=0ull;
        #pragma unroll 4
        for (int f = 0; f < 32; f++){
            ulonglong2 z0 = *(const ulonglong2*)(Zk + tn*32 + f);
            ulonglong2 z1 = *(const ulonglong2*)(Zk + (tn+16)*32 + f);
            ulonglong2 w0 = *(const ulonglong2*)(Wk + f*32 + tj);
            ulonglong2 w1 = *(const ulonglong2*)(Wk + f*32 + tj + 16);
            fma2(aA00, z0.x, w0.x); fma2(aB00, z0.y, w0.y);
            fma2(aA01, z0.x, w1.x); fma2(aB01, z0.y, w1.y);
            fma2(aA10, z1.x, w0.x); fma2(aB10, z1.y, w0.y);
            fma2(aA11, z1.x, w1.x); fma2(aB11, z1.y, w1.y);
        }
        float2 A, B;
        A = upk2(aA00); B = upk2(aB00);
        psum[(g*32 + tn   )*32 + tj   ] = A.x + A.y + B.x + B.y;
        A = upk2(aA01); B = upk2(aB01);
        psum[(g*32 + tn   )*32 + tj+16] = A.x + A.y + B.x + B.y;
        A = upk2(aA10); B = upk2(aB10);
        psum[(g*32 + tn+16)*32 + tj   ] = A.x + A.y + B.x + B.y;
        A = upk2(aA11); B = upk2(aB11);
        psum[(g*32 + tn+16)*32 + tj+16] = A.x + A.y + B.x + B.y;
    }
    __syncthreads();
    {
        int nn = tid >> 5, j = tid & 31;
        float o = psum[nn*32 + j] + psum[1024 + nn*32 + j]
                + psum[2048 + nn*32 + j] + psum[3072 + nn*32 + j];
        float bs = b2[c_in[c][0]*HID + j] + b2[c_in[c][1]*HID + j]
                 + b2[c_in[c][2]*HID + j] + b2[c_in[c][3]*HID + j];
        float v = (o + bs)*0.25f;     // hetero mean over 4 types
        int ng = blockIdx.x*32 + nn;
        out[ng*(NCH*HID) + c*HID + j] = v > 0.f ? v : 0.f;
    }
}

extern "C" void kernel_launch(void* const* d_in, const int* in_sizes, int n_in,
                              void* d_out, int out_size){
    const float* x   = (const float*)d_in[0];
    const int*   edg = (const int*)  d_in[1];
    const float* W1  = (const float*)d_in[2];
    const float* as1 = (const float*)d_in[3];
    const float* ad1 = (const float*)d_in[4];
    const float* b1  = (const float*)d_in[5];
    const float* W2  = (const float*)d_in[6];
    const float* as2 = (const float*)d_in[7];
    const float* ad2 = (const float*)d_in[8];
    const float* b2  = (const float*)d_in[9];
    float* out = (float*)d_out;

    static bool attr_set = false;
    if (!attr_set){
        cudaFuncSetAttribute(l2_gather_kernel,
                             cudaFuncAttributeMaxDynamicSharedMemorySize, 106496);
        cudaFuncSetAttribute(count_kernel,
                             cudaFuncAttributeMaxDynamicSharedMemorySize, NN*4);
        cudaFuncSetAttribute(fill2_kernel,
                             cudaFuncAttributeMaxDynamicSharedMemorySize, NN*4);
        attr_set = true;
    }

    count_kernel<<<NT*NBLK, 1024, NN*4>>>(edg);       // idx 0
    prefA_kernel<<<NT*NPCH, 256>>>();                 // idx 1
    scanC_kernel<<<NT*NCHK, 256>>>();                 // idx 2
    fill2_kernel<<<NT*NBLK, 1024, NN*4>>>(edg);       // idx 3  <- profiler window
    paramwt_kernel<<<(NT*HID*HID + 255)/256, 256>>>(W1, as1, ad1, W2, as2, ad2);
    l1_edge_kernel<<<(NT*NN + 255)/256, 256>>>(x);
    l1cs_kernel<<<NCH*NN/8, 256>>>(W1, b1);
    dim3 g2(NN/32, NCH);   // 625 x 4
    l2_gather_kernel<<<g2, 1024, 106496>>>(b2, out);
}

// round 16
// speedup vs baseline: 1.0524x; 1.0524x over previous
#include <cuda_runtime.h>
#include <cuda_fp16.h>
#include <math.h>

#define NCH 4
#define NN 20000
#define NE 320000
#define NT 16
#define HID 32
#define CHUNK 2048
#define NCHK 10    // scanC chunks (2048 nodes)
#define PCHUNK 1024
#define NPCH 20    // prefA chunks (1024 nodes)
#define CAP 64     // per-warp p-tile capacity in l2_gather
#define NBLK 16    // histogram blocks per edge type
#define SL (NE/NBLK)

// edge-type metadata: 4 spatial (c->c) then 12 inter-channel (s!=d)
__constant__ int c_src[16] = {0,1,2,3, 0,0,0, 1,1,1, 2,2,2, 3,3,3};
__constant__ int c_dst[16] = {0,1,2,3, 1,2,3, 0,2,3, 0,1,3, 0,1,2};
__constant__ int c_in[4][4]  = {{0,7,10,13},{1,4,11,14},{2,5,8,15},{3,6,9,12}};  // dst==c
__constant__ int c_out[4][4] = {{0,4,5,6},{1,7,8,9},{2,10,11,12},{3,13,14,15}};  // src==c

// scratch (static device globals; no allocation)
__device__ int    g_pc[NT*NBLK*NN];     // per-(type,block) partial counts -> prefixes
__device__ int    g_cnt[NT*NN];         // per-(type,node) total counts
__device__ int    g_off[NT*(NN+1)];
__device__ int    g_col[NT*NE];
__device__ int    g_bsum[NT*NPCH];
__device__ float4 g_za[NT*NN];          // layer1 per-(type,dst) head aggregates
__device__ __half g_y[NCH*NN*HID];      // layer1 output (post relu), fp16 (gather BW)
__device__ float4 g_s2[NT*NN];          // layer2 src scores per head
__device__ float4 g_d2[NT*NN];          // layer2 dst scores per head
__device__ float4 g_As2[NT*HID];        // W2^T @ att_src2 folded: [t][f][h]
__device__ float4 g_Ad2[NT*HID];
__device__ float4 g_SA[NT];             // layer1 folded score weights [t][h]
__device__ float4 g_DA[NT];
__device__ float4 g_Wt[NT*HID*HID];     // W2 transposed: [t][f][j] = {W2[t][f][h*32+j]}_h

__device__ __forceinline__ float lrelu(float v){ return v > 0.f ? v : 0.2f*v; }

// ---- packed f32x2 helpers (sm_103a) ----
__device__ __forceinline__ unsigned long long pk2(float lo, float hi){
    unsigned long long r;
    asm("mov.b64 %0, {%1, %2};" : "=l"(r) : "f"(lo), "f"(hi));
    return r;
}
__device__ __forceinline__ void fma2(unsigned long long& d, unsigned long long a,
                                     unsigned long long b){
    asm("fma.rn.f32x2 %0, %1, %2, %3;" : "=l"(d) : "l"(a), "l"(b), "l"(d));
}
__device__ __forceinline__ void mul2(unsigned long long& d, unsigned long long a,
                                     unsigned long long b){
    asm("mul.rn.f32x2 %0, %1, %2;" : "=l"(d) : "l"(a), "l"(b));
}
__device__ __forceinline__ void add2(unsigned long long& d, unsigned long long a,
                                     unsigned long long b){
    asm("add.rn.f32x2 %0, %1, %2;" : "=l"(d) : "l"(a), "l"(b));
}
__device__ __forceinline__ float2 upk2(unsigned long long v){
    float2 r;
    asm("mov.b64 {%0, %1}, %2;" : "=f"(r.x), "=f"(r.y) : "l"(v));
    return r;
}

// ---------------- CSR: smem histogram count (no rank storage) ----------------
__global__ void __launch_bounds__(1024) count_kernel(const int* __restrict__ edges){
    extern __shared__ int hist[];           // [NN] = 80 KB
    int b = blockIdx.x;                     // b = t*NBLK + blk
    int t = b >> 4, blk = b & 15;
    for (int i = threadIdx.x; i < NN; i += 1024) hist[i] = 0;
    __syncthreads();
    const int4* dstp = (const int4*)(edges + t*2*NE + NE + blk*SL);
    for (int i = threadIdx.x; i < SL/8; i += 1024){
        int4 dA = dstp[2*i];
        int4 dB = dstp[2*i+1];
        atomicAdd(&hist[dA.x], 1);
        atomicAdd(&hist[dA.y], 1);
        atomicAdd(&hist[dA.z], 1);
        atomicAdd(&hist[dA.w], 1);
        atomicAdd(&hist[dB.x], 1);
        atomicAdd(&hist[dB.y], 1);
        atomicAdd(&hist[dB.z], 1);
        atomicAdd(&hist[dB.w], 1);
    }
    __syncthreads();
    int* pc = g_pc + b*NN;
    for (int i = threadIdx.x; i < NN; i += 1024) pc[i] = hist[i];
}

// ---------------- merged: per-node prefix over NBLK partials + chunk sums ------
__global__ void __launch_bounds__(256) prefA_kernel(){
    __shared__ int sd[256];
    int b = blockIdx.x;                     // b = t*NPCH + chunk
    int t = b / NPCH, chunk = b % NPCH;
    int tid = threadIdx.x;
    int base = chunk*PCHUNK + tid*4;        // NN%4==0 -> base<NN implies base+4<=NN
    int v[NBLK][4];
    bool ok = base < NN;
    #pragma unroll
    for (int k = 0; k < NBLK; k++){
        int4 a = make_int4(0,0,0,0);
        if (ok) a = *(const int4*)(g_pc + (t*NBLK + k)*NN + base);
        v[k][0]=a.x; v[k][1]=a.y; v[k][2]=a.z; v[k][3]=a.w;
    }
    int cnt[4];
    int tsum = 0;
    #pragma unroll
    for (int e = 0; e < 4; e++){
        int run = 0;
        #pragma unroll
        for (int k = 0; k < NBLK; k++){
            int tmp = v[k][e];
            v[k][e] = run;                  // exclusive prefix across blocks
            run += tmp;
        }
        cnt[e] = run;
        tsum += run;
    }
    if (ok){
        #pragma unroll
        for (int k = 0; k < NBLK; k++)
            *(int4*)(g_pc + (t*NBLK + k)*NN + base) =
                make_int4(v[k][0], v[k][1], v[k][2], v[k][3]);
        *(int4*)(g_cnt + t*NN + base) = make_int4(cnt[0], cnt[1], cnt[2], cnt[3]);
    }
    sd[tid] = tsum;
    __syncthreads();
    #pragma unroll
    for (int ofs = 128; ofs > 0; ofs >>= 1){
        if (tid < ofs) sd[tid] += sd[tid+ofs];
        __syncthreads();
    }
    if (tid == 0) g_bsum[b] = sd[0];
}

// ---------------- scan: per-chunk exclusive scan -> g_off (bbase inline) -------
__global__ void __launch_bounds__(256) scanC_kernel(){
    __shared__ int sd[256];
    __shared__ int bb;
    int b = blockIdx.x;
    int t = b / NCHK, chunk = b % NCHK;
    int tid = threadIdx.x;
    if (tid == 0){
        int run = 0;
        for (int k = 0; k < 2*chunk; k++) run += g_bsum[t*NPCH + k];
        bb = run;
        if (chunk == 0) g_off[t*(NN+1)] = 0;
    }
    int base = chunk*CHUNK + tid*8;
    int c[8];
    int tsum = 0;
    bool ok = base < NN;
    {
        int4 a = make_int4(0,0,0,0), d = make_int4(0,0,0,0);
        if (ok){
            const int4* p = (const int4*)(g_cnt + t*NN + base);
            a = p[0]; d = p[1];
        }
        c[0]=a.x; c[1]=a.y; c[2]=a.z; c[3]=a.w;
        c[4]=d.x; c[5]=d.y; c[6]=d.z; c[7]=d.w;
        #pragma unroll
        for (int e = 0; e < 8; e++) tsum += c[e];
    }
    sd[tid] = tsum;
    __syncthreads();
    #pragma unroll
    for (int ofs = 1; ofs < 256; ofs <<= 1){
        int add = (tid >= ofs) ? sd[tid-ofs] : 0;
        __syncthreads();
        sd[tid] += add;
        __syncthreads();
    }
    int run = sd[tid] - tsum + bb;
    if (ok){
        #pragma unroll
        for (int e = 0; e < 8; e++){
            run += c[e];
            g_off[t*(NN+1) + base + e + 1] = run;
        }
    }
}

// ---------------- CSR: fill via seeded smem cursors ----------------
__global__ void __launch_bounds__(1024) fill2_kernel(const int* __restrict__ edges){
    extern __shared__ int cur[];            // [NN] = 80 KB
    int b = blockIdx.x;
    int t = b >> 4, blk = b & 15;
    const int* offT = g_off + t*(NN+1);
    const int* pc = g_pc + b*NN;
    for (int i = threadIdx.x; i < NN; i += 1024) cur[i] = offT[i] + pc[i];
    __syncthreads();
    const int4* srcp = (const int4*)(edges + t*2*NE + blk*SL);
    const int4* dstp = (const int4*)(edges + t*2*NE + NE + blk*SL);
    int* colT = g_col + t*NE;
    for (int i = threadIdx.x; i < SL/8; i += 1024){
        int4 sA = srcp[2*i],  sB = srcp[2*i+1];
        int4 dA = dstp[2*i],  dB = dstp[2*i+1];
        int pA0 = atomicAdd(&cur[dA.x], 1);
        int pA1 = atomicAdd(&cur[dA.y], 1);
        int pA2 = atomicAdd(&cur[dA.z], 1);
        int pA3 = atomicAdd(&cur[dA.w], 1);
        int pB0 = atomicAdd(&cur[dB.x], 1);
        int pB1 = atomicAdd(&cur[dB.y], 1);
        int pB2 = atomicAdd(&cur[dB.z], 1);
        int pB3 = atomicAdd(&cur[dB.w], 1);
        colT[pA0] = sA.x;
        colT[pA1] = sA.y;
        colT[pA2] = sA.z;
        colT[pA3] = sA.w;
        colT[pB0] = sB.x;
        colT[pB1] = sB.y;
        colT[pB2] = sB.z;
        colT[pB3] = sB.w;
    }
}

// ---------------- fold attention weights + transpose W2 (merged) ----------------
__global__ void paramwt_kernel(const float* __restrict__ W1, const float* __restrict__ as1,
                               const float* __restrict__ ad1,
                               const float* __restrict__ W2, const float* __restrict__ as2,
                               const float* __restrict__ ad2){
    int i = blockIdx.x*blockDim.x + threadIdx.x;
    if (i >= NT*HID*HID) return;
    int t = i >> 10;
    int r = i & 1023;
    int f = r >> 5, j = r & 31;
    const float* wb = W2 + (t*HID + f)*128 + j;
    g_Wt[i] = make_float4(wb[0], wb[32], wb[64], wb[96]);
    if (j < 4){
        int h = j;
        float sa = 0.f, sd = 0.f;
        const float* wrow = W2 + (t*HID + f)*128 + h*32;
        const float* arow = as2 + (t*4 + h)*32;
        const float* drow = ad2 + (t*4 + h)*32;
        #pragma unroll
        for (int c = 0; c < 32; c++){ sa += wrow[c]*arow[c]; sd += wrow[c]*drow[c]; }
        ((float*)g_As2)[(t*HID + f)*4 + h] = sa;
        ((float*)g_Ad2)[(t*HID + f)*4 + h] = sd;
        if (f == 0){
            float s1 = 0.f, d1 = 0.f;
            const float* w1 = W1 + t*128 + h*32;
            const float* a1 = as1 + (t*4 + h)*32;
            const float* dd1 = ad1 + (t*4 + h)*32;
            #pragma unroll
            for (int c = 0; c < 32; c++){ s1 += w1[c]*a1[c]; d1 += w1[c]*dd1[c]; }
            ((float*)g_SA)[t*4 + h] = s1;
            ((float*)g_DA)[t*4 + h] = d1;
        }
    }
}

// ---------------- layer-1 edge aggregation: thread per (type,dst), 4-edge ILP ----
__global__ void l1_edge_kernel(const float* __restrict__ x){
    int i = blockIdx.x*blockDim.x + threadIdx.x;
    if (i >= NT*NN) return;
    int t = i / NN, n = i - t*NN;
    float4 SAv = g_SA[t];
    float4 DAv = g_DA[t];
    float SA[4] = {SAv.x, SAv.y, SAv.z, SAv.w};
    float DA[4] = {DAv.x, DAv.y, DAv.z, DAv.w};
    float xd = x[c_dst[t]*NN + n];
    float dsc[4];
    #pragma unroll
    for (int h = 0; h < 4; h++) dsc[h] = xd * DA[h];
    const float* xs = x + c_src[t]*NN;
    const int* col = g_col + t*NE;
    int beg = g_off[t*(NN+1) + n];
    int end = g_off[t*(NN+1) + n + 1];
    float den[4] = {0,0,0,0}, acc[4] = {0,0,0,0};
    int j = beg;
    for (; j + 3 < end; j += 4){         // 4 independent x gathers in flight
        int s0 = col[j], s1 = col[j+1], s2 = col[j+2], s3 = col[j+3];
        float x0 = xs[s0], x1 = xs[s1], x2 = xs[s2], x3 = xs[s3];
        #pragma unroll
        for (int h = 0; h < 4; h++){
            float p0 = __expf(lrelu(x0*SA[h] + dsc[h]));
            float p1 = __expf(lrelu(x1*SA[h] + dsc[h]));
            float p2 = __expf(lrelu(x2*SA[h] + dsc[h]));
            float p3 = __expf(lrelu(x3*SA[h] + dsc[h]));
            den[h] += (p0 + p1) + (p2 + p3);
            acc[h] += (p0*x0 + p1*x1) + (p2*x2 + p3*x3);
        }
    }
    for (; j < end; j++){
        int s = col[j];
        float xv = xs[s];
        #pragma unroll
        for (int h = 0; h < 4; h++){
            float p = __expf(lrelu(xv*SA[h] + dsc[h]));
            den[h] += p;
            acc[h] += p*xv;
        }
    }
    float4 z;
    z.x = den[0] > 0.f ? acc[0]/den[0] : 0.f;
    z.y = den[1] > 0.f ? acc[1]/den[1] : 0.f;
    z.z = den[2] > 0.f ? acc[2]/den[2] : 0.f;
    z.w = den[3] > 0.f ? acc[3]/den[3] : 0.f;
    g_za[t*NN + n] = z;
}

// ---------------- layer-1 combine + layer-2 scores (fused, warp per node) -------
// round-13 butterfly version; scores from fp32 v, only the y store is fp16.
__global__ void l1cs_kernel(const float* __restrict__ W1, const float* __restrict__ b1){
    int wg = blockIdx.x*8 + (threadIdx.x >> 5);
    if (wg >= NCH*NN) return;
    int lane = threadIdx.x & 31;
    int c = wg / NN, n = wg - c*NN;
    int j = lane;
    float v = 0.f;
    #pragma unroll
    for (int k = 0; k < 4; k++){
        int t = c_in[c][k];
        float4 za = g_za[t*NN + n];
        const float* w = W1 + t*128;
        float o = za.x*w[j] + za.y*w[32+j] + za.z*w[64+j] + za.w*w[96+j];
        v += o*0.25f + b1[t*HID + j];
    }
    v *= 0.25f;                       // hetero mean over 4 incoming types
    v = v > 0.f ? v : 0.f;
    g_y[c*NN*HID + n*HID + j] = __float2half_rn(v);
    #pragma unroll
    for (int k = 0; k < 4; k++){
        int ts = c_out[c][k];         // this node is src for these types
        float4 a = g_As2[ts*HID + j];
        float4 s = make_float4(v*a.x, v*a.y, v*a.z, v*a.w);
        int td = c_in[c][k];          // this node is dst for these types
        float4 bq = g_Ad2[td*HID + j];
        float4 d = make_float4(v*bq.x, v*bq.y, v*bq.z, v*bq.w);
        #pragma unroll
        for (int o2 = 16; o2; o2 >>= 1){
            s.x += __shfl_xor_sync(0xffffffffu, s.x, o2);
            s.y += __shfl_xor_sync(0xffffffffu, s.y, o2);
            s.z += __shfl_xor_sync(0xffffffffu, s.z, o2);
            s.w += __shfl_xor_sync(0xffffffffu, s.w, o2);
            d.x += __shfl_xor_sync(0xffffffffu, d.x, o2);
            d.y += __shfl_xor_sync(0xffffffffu, d.y, o2);
            d.z += __shfl_xor_sync(0xffffffffu, d.z, o2);
            d.w += __shfl_xor_sync(0xffffffffu, d.w, o2);
        }
        if (lane == 0){
            g_s2[ts*NN + n] = s;
            g_d2[td*NN + n] = d;
        }
    }
}

// ---------------- layer-2 fused: softmax + gather + block-GEMM epilogue ----------
// Phase 1: warp per dst node; exp lane-parallel into p-tiles; gather stage
// PAIRED: half-warp per edge (16 lanes x half2 = one 64B fp16 y row), two
// edges per iteration, halves recombined with one 64-bit shfl at the end.
__global__ void __launch_bounds__(1024) l2_gather_kernel(const float* __restrict__ b2,
                                                         float* __restrict__ out){
    extern __shared__ float smemf[];
    float4* zsm = (float4*)smemf;                 // [4][32n][32f] f4(h): 64 KB
    float4* wbA = (float4*)(smemf + 16384);       // [32 warps][CAP]:     32 KB
    int*    cbA = (int*)  (smemf + 24576);        // [32 warps][CAP]:      8 KB
    float*  psum = (float*)wbA;                   // reused in phase 2:   16 KB
    int c = blockIdx.y;
    int tid = threadIdx.x;
    int warp = tid >> 5, lane = tid & 31;
    int half = lane >> 4, fl = lane & 15;
    int n = blockIdx.x*32 + warp;                 // grid.x = 625, exact cover
    float4* wb = wbA + warp*CAP;
    int* cb = cbA + warp*CAP;
    #pragma unroll
    for (int k = 0; k < 4; k++){
        int t = c_in[c][k];
        const __half* ysrc = g_y + c_src[t]*NN*HID;
        const int* col = g_col + t*NE;
        const float4* s2 = g_s2 + t*NN;
        int beg = g_off[t*(NN+1) + n], end = g_off[t*(NN+1) + n + 1];
        int deg = end - beg;
        float4 dv = g_d2[t*NN + n];
        float d0 = 0.f, d1 = 0.f, d2 = 0.f, d3 = 0.f;
        unsigned long long a01 = 0ull, a23 = 0ull;
        if (deg <= CAP){
            int degE = (deg + 1) & ~1;            // pad to even
            for (int base = 0; base < degE; base += 32){
                int j = base + lane;
                if (j < deg){
                    int s = col[beg + j];
                    float4 sv = s2[s];
                    float4 p;
                    p.x = __expf(lrelu(sv.x + dv.x));
                    p.y = __expf(lrelu(sv.y + dv.y));
                    p.z = __expf(lrelu(sv.z + dv.z));
                    p.w = __expf(lrelu(sv.w + dv.w));
                    d0 += p.x; d1 += p.y; d2 += p.z; d3 += p.w;
                    wb[j] = p; cb[j] = s;
                } else if (j < degE){
                    wb[j] = make_float4(0.f, 0.f, 0.f, 0.f);
                    cb[j] = 0;
                }
            }
            __syncwarp();
            #pragma unroll
            for (int o = 16; o; o >>= 1){
                d0 += __shfl_xor_sync(0xffffffffu, d0, o);
                d1 += __shfl_xor_sync(0xffffffffu, d1, o);
                d2 += __shfl_xor_sync(0xffffffffu, d2, o);
                d3 += __shfl_xor_sync(0xffffffffu, d3, o);
            }
            // paired gather: half-warp h processes edge i+h; lane owns features
            // 2*fl, 2*fl+1 via one half2 load (16 lanes cover the 64B row).
            unsigned long long cA01 = 0ull, cA23 = 0ull;   // feature 2*fl
            unsigned long long cB01 = 0ull, cB23 = 0ull;   // feature 2*fl+1
            for (int i = 0; i < degE; i += 2){
                int e = i + half;
                int s = cb[e];
                ulonglong2 pw = *(const ulonglong2*)(wb + e);
                float2 yv = __half22float2(*(const __half2*)(ysrc + s*HID + 2*fl));
                unsigned long long y0 = pk2(yv.x, yv.x);
                unsigned long long y1 = pk2(yv.y, yv.y);
                fma2(cA01, pw.x, y0); fma2(cA23, pw.y, y0);
                fma2(cB01, pw.x, y1); fma2(cB23, pw.y, y1);
            }
            // recombine halves (lane l <-> l^16 hold same features, other edges)
            add2(cA01, cA01, __shfl_xor_sync(0xffffffffu, cA01, 16));
            add2(cA23, cA23, __shfl_xor_sync(0xffffffffu, cA23, 16));
            add2(cB01, cB01, __shfl_xor_sync(0xffffffffu, cB01, 16));
            add2(cB23, cB23, __shfl_xor_sync(0xffffffffu, cB23, 16));
            unsigned long long r01 = pk2(d0 > 0.f ? __fdividef(0.25f, d0) : 0.f,
                                         d1 > 0.f ? __fdividef(0.25f, d1) : 0.f);
            unsigned long long r23 = pk2(d2 > 0.f ? __fdividef(0.25f, d2) : 0.f,
                                         d3 > 0.f ? __fdividef(0.25f, d3) : 0.f);
            // lane writes feature f = 2*fl + half (both halves have full sums)
            unsigned long long w01 = half ? cB01 : cA01;
            unsigned long long w23 = half ? cB23 : cA23;
            mul2(w01, w01, r01);
            mul2(w23, w23, r23);
            int f = 2*fl + half;
            *(ulonglong2*)(zsm + (k*32 + warp)*32 + f) = make_ulonglong2(w01, w23);
            __syncwarp();
        } else {                                  // rare fallback: recompute path
            for (int base = beg; base < end; base += 32){
                int j = base + lane;
                if (j < end){
                    int s = col[j];
                    float4 sv = s2[s];
                    d0 += __expf(lrelu(sv.x + dv.x));
                    d1 += __expf(lrelu(sv.y + dv.y));
                    d2 += __expf(lrelu(sv.z + dv.z));
                    d3 += __expf(lrelu(sv.w + dv.w));
                }
            }
            #pragma unroll
            for (int o = 16; o; o >>= 1){
                d0 += __shfl_xor_sync(0xffffffffu, d0, o);
                d1 += __shfl_xor_sync(0xffffffffu, d1, o);
                d2 += __shfl_xor_sync(0xffffffffu, d2, o);
                d3 += __shfl_xor_sync(0xffffffffu, d3, o);
            }
            for (int base = beg; base < end; base += 32){
                int j = base + lane;
                int m = min(32, end - base);
                if (j < end){
                    int s = col[j];
                    float4 sv = s2[s];
                    float4 p;
                    p.x = __expf(lrelu(sv.x + dv.x));
                    p.y = __expf(lrelu(sv.y + dv.y));
                    p.z = __expf(lrelu(sv.z + dv.z));
                    p.w = __expf(lrelu(sv.w + dv.w));
                    wb[lane] = p; cb[lane] = s;
                }
                __syncwarp();
                for (int i = 0; i < m; i++){
                    ulonglong2 pw = *(const ulonglong2*)(wb + i);
                    float yv = __half2float(ysrc[cb[i]*HID + lane]);
                    unsigned long long y2 = pk2(yv, yv);
                    fma2(a01, pw.x, y2); fma2(a23, pw.y, y2);
                }
                __syncwarp();
            }
            unsigned long long r01 = pk2(d0 > 0.f ? __fdividef(0.25f, d0) : 0.f,
                                         d1 > 0.f ? __fdividef(0.25f, d1) : 0.f);
            unsigned long long r23 = pk2(d2 > 0.f ? __fdividef(0.25f, d2) : 0.f,
                                         d3 > 0.f ? __fdividef(0.25f, d3) : 0.f);
            mul2(a01, a01, r01);
            mul2(a23, a23, r23);
            *(ulonglong2*)(zsm + (k*32 + warp)*32 + lane) = make_ulonglong2(a01, a23);
        }
    }
    __syncthreads();
    // phase 2: block GEMM, 2x2 tiles, k split over thread groups; Wt from L1
    {
        int g  = tid >> 8;            // k
        int r  = tid & 255;
        int tn = r >> 4;              // 0..15
        int tj = r & 15;              // 0..15
        const float4* Zk = zsm + g*1024;
        const float4* Wk = g_Wt + c_in[c][g]*1024;
        unsigned long long aA00=0ull, aB00=0ull, aA01=0ull, aB01=0ull;
        unsigned long long aA10=0ull, aB10=0ull, aA11=0ull, aB11=0ull;
        #pragma unroll 4
        for (int f = 0; f < 32; f++){
            ulonglong2 z0 = *(const ulonglong2*)(Zk + tn*32 + f);
            ulonglong2 z1 = *(const ulonglong2*)(Zk + (tn+16)*32 + f);
            ulonglong2 w0 = *(const ulonglong2*)(Wk + f*32 + tj);
            ulonglong2 w1 = *(const ulonglong2*)(Wk + f*32 + tj + 16);
            fma2(aA00, z0.x, w0.x); fma2(aB00, z0.y, w0.y);
            fma2(aA01, z0.x, w1.x); fma2(aB01, z0.y, w1.y);
            fma2(aA10, z1.x, w0.x); fma2(aB10, z1.y, w0.y);
            fma2(aA11, z1.x, w1.x); fma2(aB11, z1.y, w1.y);
        }
        float2 A, B;
        A = upk2(aA00); B = upk2(aB00);
        psum[(g*32 + tn   )*32 + tj   ] = A.x + A.y + B.x + B.y;
        A = upk2(aA01); B = upk2(aB01);
        psum[(g*32 + tn   )*32 + tj+16] = A.x + A.y + B.x + B.y;
        A = upk2(aA10); B = upk2(aB10);
        psum[(g*32 + tn+16)*32 + tj   ] = A.x + A.y + B.x + B.y;
        A = upk2(aA11); B = upk2(aB11);
        psum[(g*32 + tn+16)*32 + tj+16] = A.x + A.y + B.x + B.y;
    }
    __syncthreads();
    {
        int nn = tid >> 5, j = tid & 31;
        float o = psum[nn*32 + j] + psum[1024 + nn*32 + j]
                + psum[2048 + nn*32 + j] + psum[3072 + nn*32 + j];
        float bs = b2[c_in[c][0]*HID + j] + b2[c_in[c][1]*HID + j]
                 + b2[c_in[c][2]*HID + j] + b2[c_in[c][3]*HID + j];
        float v = (o + bs)*0.25f;     // hetero mean over 4 types
        int ng = blockIdx.x*32 + nn;
        out[ng*(NCH*HID) + c*HID + j] = v > 0.f ? v : 0.f;
    }
}

extern "C" void kernel_launch(void* const* d_in, const int* in_sizes, int n_in,
                              void* d_out, int out_size){
    const float* x   = (const float*)d_in[0];
    const int*   edg = (const int*)  d_in[1];
    const float* W1  = (const float*)d_in[2];
    const float* as1 = (const float*)d_in[3];
    const float* ad1 = (const float*)d_in[4];
    const float* b1  = (const float*)d_in[5];
    const float* W2  = (const float*)d_in[6];
    const float* as2 = (const float*)d_in[7];
    const float* ad2 = (const float*)d_in[8];
    const float* b2  = (const float*)d_in[9];
    float* out = (float*)d_out;

    static bool attr_set = false;
    if (!attr_set){
        cudaFuncSetAttribute(l2_gather_kernel,
                             cudaFuncAttributeMaxDynamicSharedMemorySize, 106496);
        cudaFuncSetAttribute(count_kernel,
                             cudaFuncAttributeMaxDynamicSharedMemorySize, NN*4);
        cudaFuncSetAttribute(fill2_kernel,
                             cudaFuncAttributeMaxDynamicSharedMemorySize, NN*4);
        attr_set = true;
    }

    count_kernel<<<NT*NBLK, 1024, NN*4>>>(edg);       // idx 0
    prefA_kernel<<<NT*NPCH, 256>>>();                 // idx 1
    scanC_kernel<<<NT*NCHK, 256>>>();                 // idx 2
    fill2_kernel<<<NT*NBLK, 1024, NN*4>>>(edg);       // idx 3  <- profiler window
    paramwt_kernel<<<(NT*HID*HID + 255)/256, 256>>>(W1, as1, ad1, W2, as2, ad2);
    l1_edge_kernel<<<(NT*NN + 255)/256, 256>>>(x);
    l1cs_kernel<<<(NCH*NN + 7)/8, 256>>>(W1, b1);
    dim3 g2(NN/32, NCH);   // 625 x 4
    l2_gather_kernel<<<g2, 1024, 106496>>>(b2, out);
}